// round 11
// baseline (speedup 1.0000x reference)
#include <cuda_runtime.h>

#define H      4096
#define TMAX   16384
#define EXP    8
#define FULLM  0xFFFFFFFFu
#define DEPTH  6

// Phase-1 partials: [row][16 warps][8 experts] = 8 MB
__device__ float g_scratch[(size_t)TMAX * 16 * EXP];

typedef unsigned long long u64;

__device__ __forceinline__ u64 fma2(u64 a, u64 b, u64 c) {
    u64 d; asm("fma.rn.f32x2 %0,%1,%2,%3;" : "=l"(d) : "l"(a), "l"(b), "l"(c)); return d;
}
__device__ __forceinline__ u64 mul2(u64 a, u64 b) {
    u64 d; asm("mul.rn.f32x2 %0,%1,%2;" : "=l"(d) : "l"(a), "l"(b)); return d;
}
__device__ __forceinline__ float hadd2(u64 v) {
    float lo = __uint_as_float((unsigned)v);
    float hi = __uint_as_float((unsigned)(v >> 32));
    return lo + hi;
}

// Reduce 8 per-lane values across 32 lanes (vector-halving butterfly, 9 shfls).
// Result: lane 4e holds the sum for expert e.
__device__ __forceinline__ float reduce8(float a[8]) {
    const int lane = threadIdx.x & 31;
    {
        bool hi = (lane & 16) != 0;
        float s0 = hi ? a[0] : a[4];
        float s1 = hi ? a[1] : a[5];
        float s2 = hi ? a[2] : a[6];
        float s3 = hi ? a[3] : a[7];
        s0 = __shfl_xor_sync(FULLM, s0, 16);
        s1 = __shfl_xor_sync(FULLM, s1, 16);
        s2 = __shfl_xor_sync(FULLM, s2, 16);
        s3 = __shfl_xor_sync(FULLM, s3, 16);
        a[0] = (hi ? a[4] : a[0]) + s0;
        a[1] = (hi ? a[5] : a[1]) + s1;
        a[2] = (hi ? a[6] : a[2]) + s2;
        a[3] = (hi ? a[7] : a[3]) + s3;
    }
    {
        bool hi = (lane & 8) != 0;
        float s0 = hi ? a[0] : a[2];
        float s1 = hi ? a[1] : a[3];
        s0 = __shfl_xor_sync(FULLM, s0, 8);
        s1 = __shfl_xor_sync(FULLM, s1, 8);
        a[0] = (hi ? a[2] : a[0]) + s0;
        a[1] = (hi ? a[3] : a[1]) + s1;
    }
    {
        bool hi = (lane & 4) != 0;
        float s0 = hi ? a[0] : a[1];
        s0 = __shfl_xor_sync(FULLM, s0, 4);
        a[0] = (hi ? a[1] : a[0]) + s0;
    }
    float v = a[0];
    v += __shfl_xor_sync(FULLM, v, 2);
    v += __shfl_xor_sync(FULLM, v, 1);
    return v;
}

// ── Phase 1: streaming GEMV partials.
//   512 threads; thread owns 8 k (float4 at k=4*tid and k=2048+4*tid).
//   DEPTH-6 register ring of row chunks: 48KB in flight per SM covers the
//   577-cycle DRAM latency with 3x margin. No shared memory at all —
//   crossbar carries only the 9 reduction shuffles per warp-row.
__global__ void __launch_bounds__(512, 1)
router_p1(const float* __restrict__ x, const float* __restrict__ W, int T) {
    const int tid  = threadIdx.x;
    const int lane = tid & 31;
    const int warp = tid >> 5;
    const int nb   = gridDim.x;

    // W regs: 8 experts x 2 chunks x 16B = 64 regs
    u64 wa0[EXP], wa1[EXP], wb0[EXP], wb1[EXP];
#pragma unroll
    for (int e = 0; e < EXP; e++) {
        ulonglong2 ta = *reinterpret_cast<const ulonglong2*>(W + e * H + tid * 4);
        ulonglong2 tb = *reinterpret_cast<const ulonglong2*>(W + e * H + 2048 + tid * 4);
        wa0[e] = ta.x; wa1[e] = ta.y;
        wb0[e] = tb.x; wb1[e] = tb.y;
    }

    const ulonglong2* x2 = reinterpret_cast<const ulonglong2*>(x);
    const int strideR = H / 4;              // 1024 ulonglong2 per row
    const int idxA = tid;                   // chunk A slot
    const int idxB = tid + 512;             // chunk B slot

    const int r0 = blockIdx.x;

    // prologue: fill DEPTH rows into the register ring
    ulonglong2 bufA[DEPTH], bufB[DEPTH];
#pragma unroll
    for (int s = 0; s < DEPTH; s++) {
        int r = r0 + s * nb;
        bufA[s] = make_ulonglong2(0ull, 0ull);
        bufB[s] = make_ulonglong2(0ull, 0ull);
        if (r < T) {
            bufA[s] = x2[(size_t)r * strideR + idxA];
            bufB[s] = x2[(size_t)r * strideR + idxB];
        }
    }

    for (int r = r0; r < T; r += DEPTH * nb) {
#pragma unroll
        for (int s = 0; s < DEPTH; s++) {
            int rr = r + s * nb;
            if (rr >= T) break;

            ulonglong2 ca = bufA[s], cb = bufB[s];

            // refill this slot with row rr + DEPTH*nb (issues LDG early)
            int rp = rr + DEPTH * nb;
            if (rp < T) {
                bufA[s] = x2[(size_t)rp * strideR + idxA];
                bufB[s] = x2[(size_t)rp * strideR + idxB];
            }

            float a8[EXP];
#pragma unroll
            for (int e = 0; e < EXP; e++) {
                u64 acc = mul2(ca.x, wa0[e]);
                acc = fma2(ca.y, wa1[e], acc);
                acc = fma2(cb.x, wb0[e], acc);
                acc = fma2(cb.y, wb1[e], acc);
                a8[e] = hadd2(acc);
            }

            float v = reduce8(a8);
            if ((lane & 3) == 0)
                g_scratch[((size_t)rr * 16 + warp) * EXP + (lane >> 2)] = v;
        }
    }
}

// ── Phase 2: TWO rows per warp. Lane = (row-half lane>>4, slot lane&15).
//   Butterfly over masks {8,4,2}+1 reduces both rows with 8 shfls total;
//   softmax / broadcast / top-2 all stay inside each 16-lane half.
__global__ void __launch_bounds__(256)
router_p2(int T, float* __restrict__ out, int flags) {
    const int lane  = threadIdx.x & 31;
    const int warpG = (blockIdx.x * 256 + threadIdx.x) >> 5;
    const int half  = lane >> 4;            // which of 2 rows
    const int hl    = lane & 15;            // slot within the row
    const int r     = warpG * 2 + half;
    if (warpG * 2 >= T) return;             // T is even

    const float4* p = reinterpret_cast<const float4*>(g_scratch + ((size_t)r * 16 + hl) * EXP);
    float4 u = p[0], v = p[1];
    float a[EXP] = {u.x, u.y, u.z, u.w, v.x, v.y, v.z, v.w};

    // butterfly over masks {8,4,2}: after this, lane (within its half) holds
    // partial for expert e = 4*b3 + 2*b2 + b1, pairs (bit0) then summed.
    {
        bool hi = (lane & 8) != 0;
        float s0 = hi ? a[0] : a[4];
        float s1 = hi ? a[1] : a[5];
        float s2 = hi ? a[2] : a[6];
        float s3 = hi ? a[3] : a[7];
        s0 = __shfl_xor_sync(FULLM, s0, 8);
        s1 = __shfl_xor_sync(FULLM, s1, 8);
        s2 = __shfl_xor_sync(FULLM, s2, 8);
        s3 = __shfl_xor_sync(FULLM, s3, 8);
        a[0] = (hi ? a[4] : a[0]) + s0;
        a[1] = (hi ? a[5] : a[1]) + s1;
        a[2] = (hi ? a[6] : a[2]) + s2;
        a[3] = (hi ? a[7] : a[3]) + s3;
    }
    {
        bool hi = (lane & 4) != 0;
        float s0 = hi ? a[0] : a[2];
        float s1 = hi ? a[1] : a[3];
        s0 = __shfl_xor_sync(FULLM, s0, 4);
        s1 = __shfl_xor_sync(FULLM, s1, 4);
        a[0] = (hi ? a[2] : a[0]) + s0;
        a[1] = (hi ? a[3] : a[1]) + s1;
    }
    {
        bool hi = (lane & 2) != 0;
        float s0 = hi ? a[0] : a[1];
        s0 = __shfl_xor_sync(FULLM, s0, 2);
        a[0] = (hi ? a[1] : a[0]) + s0;
    }
    float t = a[0];
    t += __shfl_xor_sync(FULLM, t, 1);
    // now lanes 2e and 2e+1 (within each half) hold logit[e]

    // softmax within the 16-lane half (orbit masks {8,4,2})
    float m = t;
    m = fmaxf(m, __shfl_xor_sync(FULLM, m, 8));
    m = fmaxf(m, __shfl_xor_sync(FULLM, m, 4));
    m = fmaxf(m, __shfl_xor_sync(FULLM, m, 2));
    float pz = __expf(t - m);
    float sden = pz;
    sden += __shfl_xor_sync(FULLM, sden, 8);
    sden += __shfl_xor_sync(FULLM, sden, 4);
    sden += __shfl_xor_sync(FULLM, sden, 2);
    float sc = __fdividef(pz, sden);

    // broadcast all 8 scores within the half (expert j lives at lane 2j)
    float se[EXP];
#pragma unroll
    for (int j = 0; j < EXP; j++)
        se[j] = __shfl_sync(FULLM, sc, (lane & 16) | (2 * j));

    // scores: two STG.128 per row (half-lanes 0 and 1)
    if (hl < 2) {
        float4 o = hl ? make_float4(se[4], se[5], se[6], se[7])
                      : make_float4(se[0], se[1], se[2], se[3]);
        reinterpret_cast<float4*>(out + (size_t)r * EXP)[hl] = o;
    }

    // flat top-2 (ties -> lower index, matching lax.top_k)
    float v1 = se[0]; int i1 = 0;
#pragma unroll
    for (int j = 1; j < EXP; j++)
        if (se[j] > v1) { v1 = se[j]; i1 = j; }
    float v2 = -1.0f; int i2 = 0;
#pragma unroll
    for (int j = 0; j < EXP; j++)
        if (j != i1 && se[j] > v2) { v2 = se[j]; i2 = j; }

    if (hl == 2 && (flags & 1)) {
        float* outW = out + (size_t)T * EXP;
        outW[(size_t)r * 2 + 0] = v1;
        outW[(size_t)r * 2 + 1] = v2;
    }
    if (hl == 3 && (flags & 2)) {
        float* outI = out + (size_t)T * (EXP + 2);
        outI[(size_t)r * 2 + 0] = (float)i1;
        outI[(size_t)r * 2 + 1] = (float)i2;
    }
}

extern "C" void kernel_launch(void* const* d_in, const int* in_sizes, int n_in,
                              void* d_out, int out_size) {
    const float* x = (const float*)d_in[0];
    const float* W = (const float*)d_in[1];

    int T = in_sizes[0] / H;  // 16384

    int dev = 0;
    cudaGetDevice(&dev);
    int sm = 148;
    cudaDeviceGetAttribute(&sm, cudaDevAttrMultiProcessorCount, dev);

    int flags = 0;
    if (out_size >= T * (EXP + 2)) flags |= 1;
    if (out_size >= T * (EXP + 4)) flags |= 2;

    router_p1<<<sm, 512>>>(x, W, T);
    int blocks2 = ((T / 2) * 32 + 255) / 256;   // 2 rows per warp
    router_p2<<<blocks2, 256>>>(T, (float*)d_out, flags);
}

// round 12
// speedup vs baseline: 1.6917x; 1.6917x over previous
#include <cuda_runtime.h>

#define H      4096
#define TMAX   16384
#define EXP    8
#define FULLM  0xFFFFFFFFu
#define STAGES 12
#define ROWB   16384            // bytes per row stage (full 4096-float row)

// Phase-1 partials: [row][16 warps][8 experts] = 8 MB
__device__ float g_scratch[(size_t)TMAX * 16 * EXP];

typedef unsigned long long u64;

__device__ __forceinline__ u64 fma2(u64 a, u64 b, u64 c) {
    u64 d; asm("fma.rn.f32x2 %0,%1,%2,%3;" : "=l"(d) : "l"(a), "l"(b), "l"(c)); return d;
}
__device__ __forceinline__ u64 mul2(u64 a, u64 b) {
    u64 d; asm("mul.rn.f32x2 %0,%1,%2;" : "=l"(d) : "l"(a), "l"(b)); return d;
}
__device__ __forceinline__ float hadd2(u64 v) {
    float lo = __uint_as_float((unsigned)v);
    float hi = __uint_as_float((unsigned)(v >> 32));
    return lo + hi;
}
__device__ __forceinline__ void lds128(u64& a, u64& b, unsigned addr) {
    asm volatile("ld.shared.v2.u64 {%0,%1},[%2];" : "=l"(a), "=l"(b) : "r"(addr));
}
__device__ __forceinline__ void cp16(unsigned saddr, const void* gaddr) {
    asm volatile("cp.async.cg.shared.global [%0], [%1], 16;" :: "r"(saddr), "l"(gaddr));
}
__device__ __forceinline__ void cp_commit() {
    asm volatile("cp.async.commit_group;" ::: "memory");
}
__device__ __forceinline__ void cp_waitN() {
    asm volatile("cp.async.wait_group %0;" :: "n"(STAGES - 1) : "memory");
}

// Reduce 8 per-lane values across 32 lanes (vector-halving butterfly, 9 shfls).
// Result: lane 4e holds the sum for expert e.
__device__ __forceinline__ float reduce8(float a[8]) {
    const int lane = threadIdx.x & 31;
    {
        bool hi = (lane & 16) != 0;
        float s0 = hi ? a[0] : a[4];
        float s1 = hi ? a[1] : a[5];
        float s2 = hi ? a[2] : a[6];
        float s3 = hi ? a[3] : a[7];
        s0 = __shfl_xor_sync(FULLM, s0, 16);
        s1 = __shfl_xor_sync(FULLM, s1, 16);
        s2 = __shfl_xor_sync(FULLM, s2, 16);
        s3 = __shfl_xor_sync(FULLM, s3, 16);
        a[0] = (hi ? a[4] : a[0]) + s0;
        a[1] = (hi ? a[5] : a[1]) + s1;
        a[2] = (hi ? a[6] : a[2]) + s2;
        a[3] = (hi ? a[7] : a[3]) + s3;
    }
    {
        bool hi = (lane & 8) != 0;
        float s0 = hi ? a[0] : a[2];
        float s1 = hi ? a[1] : a[3];
        s0 = __shfl_xor_sync(FULLM, s0, 8);
        s1 = __shfl_xor_sync(FULLM, s1, 8);
        a[0] = (hi ? a[2] : a[0]) + s0;
        a[1] = (hi ? a[3] : a[1]) + s1;
    }
    {
        bool hi = (lane & 4) != 0;
        float s0 = hi ? a[0] : a[1];
        s0 = __shfl_xor_sync(FULLM, s0, 4);
        a[0] = (hi ? a[1] : a[0]) + s0;
    }
    float v = a[0];
    v += __shfl_xor_sync(FULLM, v, 2);
    v += __shfl_xor_sync(FULLM, v, 1);
    return v;
}

// ── Phase 1: streaming GEMV partials (proven R6 shape, deeper pipeline).
//   512 threads; thread owns 8 k: float4 at k=4*tid and k=2048+4*tid.
//   12-deep per-thread cp.async pipeline into private smem slots (no block
//   sync — each thread reads only bytes it copied).
__global__ void __launch_bounds__(512, 1)
router_p1(const float* __restrict__ x, const float* __restrict__ W, int T) {
    extern __shared__ char smem[];   // STAGES * 16KB = 192KB

    const int tid  = threadIdx.x;
    const int lane = tid & 31;
    const int warp = tid >> 5;
    const int nb   = gridDim.x;

    // W regs: 8 experts x 2 chunks x 16B = 64 regs
    u64 wa0[EXP], wa1[EXP], wb0[EXP], wb1[EXP];
#pragma unroll
    for (int e = 0; e < EXP; e++) {
        ulonglong2 ta = *reinterpret_cast<const ulonglong2*>(W + e * H + tid * 4);
        ulonglong2 tb = *reinterpret_cast<const ulonglong2*>(W + e * H + 2048 + tid * 4);
        wa0[e] = ta.x; wa1[e] = ta.y;
        wb0[e] = tb.x; wb1[e] = tb.y;
    }

    unsigned sbase;
    asm("{ .reg .u64 t; cvta.to.shared.u64 t, %1; cvt.u32.u64 %0, t; }"
        : "=r"(sbase) : "l"(smem));
    const unsigned myA = sbase + tid * 16;          // chunk A slot (bytes [0,8K))
    const unsigned myB = myA + 8192;                // chunk B slot (bytes [8K,16K))

    const char* xg = reinterpret_cast<const char*>(x);
    const size_t offA = (size_t)tid * 16;
    const size_t offB = offA + 8192;

    const int r0 = blockIdx.x;

    // prologue: fill STAGES groups
#pragma unroll
    for (int s = 0; s < STAGES; s++) {
        int r = r0 + s * nb;
        if (r < T) {
            cp16(myA + s * ROWB, xg + (size_t)r * ROWB + offA);
            cp16(myB + s * ROWB, xg + (size_t)r * ROWB + offB);
        }
        cp_commit();
    }

    int s = 0;
    for (int r = r0; r < T; r += nb) {
        cp_waitN();
        __syncwarp();

        u64 ax0, ax1, bx0, bx1;
        lds128(ax0, ax1, myA + s * ROWB);
        lds128(bx0, bx1, myB + s * ROWB);

        float a8[EXP];
#pragma unroll
        for (int e = 0; e < EXP; e++) {
            u64 acc = mul2(ax0, wa0[e]);
            acc = fma2(ax1, wa1[e], acc);
            acc = fma2(bx0, wb0[e], acc);
            acc = fma2(bx1, wb1[e], acc);
            a8[e] = hadd2(acc);
        }

        float v = reduce8(a8);
        if ((lane & 3) == 0)
            g_scratch[((size_t)r * 16 + warp) * EXP + (lane >> 2)] = v;

        int rp = r + STAGES * nb;
        if (rp < T) {
            cp16(myA + s * ROWB, xg + (size_t)rp * ROWB + offA);
            cp16(myB + s * ROWB, xg + (size_t)rp * ROWB + offB);
        }
        cp_commit();

        s = (s == STAGES - 1) ? 0 : s + 1;
    }
}

// ── Phase 2: FOUR rows per warp (octet decomposition; best-measured p2).
//   Lane = (row lane>>3, slot lane&7). Each lane folds scratch slots ol and
//   ol+8 locally, then 7-shfl octet butterfly; octet lane e holds logit[e].
__global__ void __launch_bounds__(256)
router_p2(int T, float* __restrict__ out, int flags) {
    const int lane  = threadIdx.x & 31;
    const int warpG = (blockIdx.x * 256 + threadIdx.x) >> 5;
    const int oct   = lane >> 3;   // which of 4 rows
    const int ol    = lane & 7;    // octet lane = slot / expert
    const int r     = warpG * 4 + oct;
    if (warpG * 4 >= T) return;    // full-warp guard (T % 4 == 0)

    const float4* p = reinterpret_cast<const float4*>(g_scratch + ((size_t)r * 16 + ol) * EXP);
    const float4* q = reinterpret_cast<const float4*>(g_scratch + ((size_t)r * 16 + ol + 8) * EXP);
    float4 u0 = p[0], v0 = p[1], u1 = q[0], v1q = q[1];
    float a[EXP] = {u0.x + u1.x, u0.y + u1.y, u0.z + u1.z, u0.w + u1.w,
                    v0.x + v1q.x, v0.y + v1q.y, v0.z + v1q.z, v0.w + v1q.w};

    // octet butterfly: masks {4,2,1}; after this, octet lane e holds logit[e]
    {
        bool hi = (lane & 4) != 0;
        float s0 = hi ? a[0] : a[4];
        float s1 = hi ? a[1] : a[5];
        float s2 = hi ? a[2] : a[6];
        float s3 = hi ? a[3] : a[7];
        s0 = __shfl_xor_sync(FULLM, s0, 4);
        s1 = __shfl_xor_sync(FULLM, s1, 4);
        s2 = __shfl_xor_sync(FULLM, s2, 4);
        s3 = __shfl_xor_sync(FULLM, s3, 4);
        a[0] = (hi ? a[4] : a[0]) + s0;
        a[1] = (hi ? a[5] : a[1]) + s1;
        a[2] = (hi ? a[6] : a[2]) + s2;
        a[3] = (hi ? a[7] : a[3]) + s3;
    }
    {
        bool hi = (lane & 2) != 0;
        float s0 = hi ? a[0] : a[2];
        float s1 = hi ? a[1] : a[3];
        s0 = __shfl_xor_sync(FULLM, s0, 2);
        s1 = __shfl_xor_sync(FULLM, s1, 2);
        a[0] = (hi ? a[2] : a[0]) + s0;
        a[1] = (hi ? a[3] : a[1]) + s1;
    }
    {
        bool hi = (lane & 1) != 0;
        float s0 = hi ? a[0] : a[1];
        s0 = __shfl_xor_sync(FULLM, s0, 1);
        a[0] = (hi ? a[1] : a[0]) + s0;
    }
    float t = a[0];   // octet lane e holds logit[e] of its row

    // softmax within octet (masks {4,2,1})
    float m = t;
    m = fmaxf(m, __shfl_xor_sync(FULLM, m, 4));
    m = fmaxf(m, __shfl_xor_sync(FULLM, m, 2));
    m = fmaxf(m, __shfl_xor_sync(FULLM, m, 1));
    float pz = __expf(t - m);
    float sden = pz;
    sden += __shfl_xor_sync(FULLM, sden, 4);
    sden += __shfl_xor_sync(FULLM, sden, 2);
    sden += __shfl_xor_sync(FULLM, sden, 1);
    float sc = __fdividef(pz, sden);

    // broadcast all 8 scores within the octet
    float se[EXP];
#pragma unroll
    for (int j = 0; j < EXP; j++)
        se[j] = __shfl_sync(FULLM, sc, (lane & 24) | j);

    // scores: two STG.128 per row (octet lanes 0 and 1)
    if (ol < 2) {
        float4 o = ol ? make_float4(se[4], se[5], se[6], se[7])
                      : make_float4(se[0], se[1], se[2], se[3]);
        reinterpret_cast<float4*>(out + (size_t)r * EXP)[ol] = o;
    }

    // flat top-2 (ties -> lower index, matching lax.top_k)
    float w1 = se[0]; int i1 = 0;
#pragma unroll
    for (int j = 1; j < EXP; j++)
        if (se[j] > w1) { w1 = se[j]; i1 = j; }
    float w2 = -1.0f; int i2 = 0;
#pragma unroll
    for (int j = 0; j < EXP; j++)
        if (j != i1 && se[j] > w2) { w2 = se[j]; i2 = j; }

    if (ol == 2 && (flags & 1)) {
        float* outW = out + (size_t)T * EXP;
        outW[(size_t)r * 2 + 0] = w1;
        outW[(size_t)r * 2 + 1] = w2;
    }
    if (ol == 3 && (flags & 2)) {
        float* outI = out + (size_t)T * (EXP + 2);
        outI[(size_t)r * 2 + 0] = (float)i1;
        outI[(size_t)r * 2 + 1] = (float)i2;
    }
}

extern "C" void kernel_launch(void* const* d_in, const int* in_sizes, int n_in,
                              void* d_out, int out_size) {
    const float* x = (const float*)d_in[0];
    const float* W = (const float*)d_in[1];

    int T = in_sizes[0] / H;  // 16384

    int dev = 0;
    cudaGetDevice(&dev);
    int sm = 148;
    cudaDeviceGetAttribute(&sm, cudaDevAttrMultiProcessorCount, dev);

    int flags = 0;
    if (out_size >= T * (EXP + 2)) flags |= 1;
    if (out_size >= T * (EXP + 4)) flags |= 2;

    static int smemSet = 0;
    if (!smemSet) {
        cudaFuncSetAttribute(router_p1, cudaFuncAttributeMaxDynamicSharedMemorySize,
                             STAGES * ROWB);
        smemSet = 1;
    }

    router_p1<<<sm, 512, STAGES * ROWB>>>(x, W, T);
    int blocks2 = ((T / 4) * 32 + 255) / 256;   // 4 rows per warp
    router_p2<<<blocks2, 256>>>(T, (float*)d_out, flags);
}